// round 14
// baseline (speedup 1.0000x reference)
#include <cuda_runtime.h>
#include <cuda_fp16.h>
#include <math.h>
#include <float.h>

#define NH 8
#define SEQ 4096
#define DH 128
#define LQ 64
#define VTOPK 1024
#define STOPK 2048
#define FORCE_V 30
#define FORCE_S 100
#define SCALE 0.08838834764831845f
#define NW (SEQ / 32)
#define QS_STRIDE 132
#define NPAIR (NH * SEQ * DH / 2)

// ---------------- device scratch ----------------
__device__ float    g_probs[NH * LQ * SEQ];
__device__ float    g_rowinv[NH * LQ];
__device__ float    g_vert [NH * SEQ];
__device__ float    g_slash[NH * SEQ];
__device__ unsigned g_vbits[NH * NW];
__device__ unsigned g_sbits[NH * NW];
// fp16, 2 elems packed per u32 (low = even index)
__device__ unsigned g_q[NPAIR], g_k[NPAIR], g_v[NPAIR];

// ---------------- helpers ----------------
__device__ __forceinline__ void cpa16(unsigned dst, const void* src) {
    asm volatile("cp.async.cg.shared.global [%0], [%1], 16;\n" :: "r"(dst), "l"(src));
}
__device__ __forceinline__ void cpa_commit() { asm volatile("cp.async.commit_group;\n" ::); }
__device__ __forceinline__ void cpa_wait0()  { asm volatile("cp.async.wait_group 0;\n" ::); }

__device__ __forceinline__ void ldsm4(unsigned* r, unsigned a) {
    asm volatile("ldmatrix.sync.aligned.m8n8.x4.shared.b16 {%0,%1,%2,%3}, [%4];"
        : "=r"(r[0]), "=r"(r[1]), "=r"(r[2]), "=r"(r[3]) : "r"(a));
}
__device__ __forceinline__ void ldsm4t(unsigned* r, unsigned a) {
    asm volatile("ldmatrix.sync.aligned.m8n8.x4.trans.shared.b16 {%0,%1,%2,%3}, [%4];"
        : "=r"(r[0]), "=r"(r[1]), "=r"(r[2]), "=r"(r[3]) : "r"(a));
}
__device__ __forceinline__ void mma16(float* d, const unsigned* a, unsigned b0, unsigned b1) {
    asm volatile("mma.sync.aligned.m16n8k16.row.col.f32.f16.f16.f32 "
        "{%0,%1,%2,%3}, {%4,%5,%6,%7}, {%8,%9}, {%0,%1,%2,%3};"
        : "+f"(d[0]), "+f"(d[1]), "+f"(d[2]), "+f"(d[3])
        : "r"(a[0]), "r"(a[1]), "r"(a[2]), "r"(a[3]), "r"(b0), "r"(b1));
}
__device__ __forceinline__ unsigned pk2h(float x, float y) {
    __half2 t = __floats2half2_rn(x, y);
    return *(unsigned*)&t;
}

// ---------------- kernel A: exp-scores for last 64 queries (+ fused fp16 prep) ----------------
__global__ void pattern_kernel(const float* __restrict__ q, const float* __restrict__ k,
                               const float* __restrict__ v) {
    extern __shared__ float psm[];
    float* Qs = psm;
    float* Ks = Qs + 64 * QS_STRIDE;
    int h = blockIdx.y, j0 = blockIdx.x * 128;
    int tid = threadIdx.x, ty = tid >> 4, tx = tid & 15;

    for (int e = tid; e < 64 * 32; e += 256) {
        int r = e >> 5, c = e & 31;
        float4 t = *(const float4*)&q[((size_t)(h * SEQ + SEQ - LQ + r)) * DH + (c << 2)];
        t.x *= SCALE; t.y *= SCALE; t.z *= SCALE; t.w *= SCALE;
        *(float4*)&Qs[r * QS_STRIDE + (c << 2)] = t;
    }
    for (int e = tid; e < 128 * 32; e += 256) {
        int r = e >> 5, c = e & 31;
        *(float4*)&Ks[r * 128 + ((c ^ (r >> 2)) << 2)] =
            *(const float4*)&k[((size_t)(h * SEQ + j0 + r)) * DH + (c << 2)];
    }
    __syncthreads();

    float s[4][8];
    #pragma unroll
    for (int a = 0; a < 4; a++)
        #pragma unroll
        for (int b = 0; b < 8; b++) s[a][b] = 0.f;

    #pragma unroll 4
    for (int c = 0; c < 32; c++) {
        float4 qv[4], kv[8];
        #pragma unroll
        for (int a = 0; a < 4; a++)
            qv[a] = *(const float4*)&Qs[(ty * 4 + a) * QS_STRIDE + (c << 2)];
        #pragma unroll
        for (int b = 0; b < 8; b++) {
            int r = tx * 8 + b;
            kv[b] = *(const float4*)&Ks[r * 128 + ((c ^ (r >> 2)) << 2)];
        }
        #pragma unroll
        for (int a = 0; a < 4; a++)
            #pragma unroll
            for (int b = 0; b < 8; b++)
                s[a][b] += qv[a].x * kv[b].x + qv[a].y * kv[b].y
                         + qv[a].z * kv[b].z + qv[a].w * kv[b].w;
    }
    #pragma unroll
    for (int a = 0; a < 4; a++) {
        int row = ty * 4 + a, qpos = SEQ - LQ + row;
        float p[8];
        #pragma unroll
        for (int b = 0; b < 8; b++) {
            int j = j0 + tx * 8 + b;
            p[b] = (j <= qpos) ? __expf(s[a][b]) : 0.f;
        }
        float* dst = &g_probs[((size_t)(h * LQ + row)) * SEQ + j0 + tx * 8];
        *(float4*)&dst[0] = make_float4(p[0], p[1], p[2], p[3]);
        *(float4*)&dst[4] = make_float4(p[4], p[5], p[6], p[7]);
    }

    // fused fp16 prep (grid-stride over all pairs; independent of work above)
    int gblk = blockIdx.y * gridDim.x + blockIdx.x;          // 0..255
    for (int i = gblk * 256 + tid; i < NPAIR; i += 256 * 256) {
        float2 a = ((const float2*)q)[i];
        g_q[i] = pk2h(a.x * SCALE, a.y * SCALE);
        a = ((const float2*)k)[i];
        g_k[i] = pk2h(a.x, a.y);
        a = ((const float2*)v)[i];
        g_v[i] = pk2h(a.x, a.y);
    }
}

// ---------------- kernel B1: deterministic row sums ----------------
__global__ void rowsum_kernel() {
    int b = blockIdx.x;
    int h = b >> 6, r = b & 63;
    const float* rowp = &g_probs[((size_t)(h * LQ + r)) * SEQ];
    int tid = threadIdx.x;              // 128
    float s = 0.f;
    for (int j = tid; j < SEQ; j += 128) s += rowp[j];
    __shared__ float red[128];
    red[tid] = s; __syncthreads();
    #pragma unroll
    for (int st = 64; st > 0; st >>= 1) {
        if (tid < st) red[tid] += red[tid + st];
        __syncthreads();
    }
    if (tid == 0) g_rowinv[h * LQ + r] = 1.0f / red[0];
}

// ---------------- kernel B2: vertical + slash ----------------
__global__ void reduce_kernel() {
    int h = blockIdx.x, seg = blockIdx.y;   // grid (NH, 32), 128 threads
    int tid = threadIdx.x;
    __shared__ float inv[LQ];
    if (tid < LQ) inv[tid] = g_rowinv[h * LQ + tid];
    __syncthreads();
    const float* pb = &g_probs[(size_t)h * LQ * SEQ];
    int j = seg * 128 + tid;
    float s = 0.f;
    #pragma unroll 8
    for (int lq = 0; lq < LQ; lq++) s += pb[(size_t)lq * SEQ + j] * inv[lq];
    g_vert[h * SEQ + j] = (j < FORCE_V) ? INFINITY : s;
    float t = 0.f;
    #pragma unroll 8
    for (int lq = 0; lq < LQ; lq++) {
        int idx = (SEQ - LQ) + lq - j;
        if (idx >= 0) t += pb[(size_t)lq * SEQ + idx] * inv[lq];
    }
    g_slash[h * SEQ + j] = (j < FORCE_S) ? INFINITY : t;
}

// ---------------- kernel C: exact top-k via radix select (parallel scans) ----------------
__global__ void topk_kernel() {
    int which = blockIdx.x, h = blockIdx.y;
    const float* arr = which ? &g_slash[h * SEQ] : &g_vert[h * SEQ];
    unsigned*   bits = which ? &g_sbits[h * NW]  : &g_vbits[h * NW];
    const int K = which ? STOPK : VTOPK;

    __shared__ unsigned vals[SEQ];
    __shared__ unsigned hist[256];
    __shared__ int s_b;
    __shared__ unsigned gtw[NW], eqw[NW], wcnt[NW], scan[NW];
    int tid = threadIdx.x;              // 256

    for (int i = tid; i < SEQ; i += 256) vals[i] = __float_as_uint(arr[i]);
    __syncthreads();

    unsigned prefix = 0; int remaining = K;
    #pragma unroll
    for (int pass = 3; pass >= 0; pass--) {
        int shift = pass * 8;
        hist[tid] = 0u;
        if (tid == 0) s_b = 0;
        __syncthreads();
        unsigned long long ph = (unsigned long long)prefix >> (shift + 8);
        for (int i = tid; i < SEQ; i += 256) {
            unsigned v = vals[i];
            if (((unsigned long long)v >> (shift + 8)) == ph)
                atomicAdd(&hist[(v >> shift) & 255u], 1u);
        }
        __syncthreads();
        // parallel suffix sum: hist[b] := sum of hist[b..255]
        #pragma unroll
        for (int off = 1; off < 256; off <<= 1) {
            unsigned add = (tid + off < 256) ? hist[tid + off] : 0u;
            __syncthreads();
            hist[tid] += add;
            __syncthreads();
        }
        if ((int)hist[tid] >= remaining) atomicMax(&s_b, tid);
        __syncthreads();
        int b = s_b;
        remaining -= (b < 255) ? (int)hist[b + 1] : 0;
        prefix |= ((unsigned)b << shift);
        __syncthreads();
    }

    if (tid < NW) {
        unsigned gm = 0, em = 0;
        #pragma unroll 8
        for (int b = 0; b < 32; b++) {
            unsigned v = vals[tid * 32 + b];
            gm |= (v > prefix ? 1u : 0u) << b;
            em |= (v == prefix ? 1u : 0u) << b;
        }
        gtw[tid] = gm; eqw[tid] = em;
        wcnt[tid] = __popc(em);
        scan[tid] = __popc(em);
    }
    __syncthreads();
    #pragma unroll
    for (int off = 1; off < NW; off <<= 1) {
        unsigned add = (tid < NW && tid >= off) ? scan[tid - off] : 0u;
        __syncthreads();
        if (tid < NW) scan[tid] += add;
        __syncthreads();
    }
    if (tid < NW) {
        unsigned em = eqw[tid], sel = 0;
        int rank = (int)(scan[tid] - wcnt[tid]);
        while (em) {
            int b = __ffs(em) - 1;
            if (rank < remaining) sel |= 1u << b;
            rank++;
            em &= em - 1;
        }
        bits[tid] = gtw[tid] | sel;
    }
}

// ---------------- kernel D: tensor-core masked flash attention ----------------
// 64-row q tiles, 128 threads, 2 CTAs/SM.
// smem: Q 0..16K, vb@16384(512B), sb@16896(512B), stages @17408: each 32K = K(16K) V(16K).
#define SM_Q  0
#define SM_VB 16384
#define SM_SB 16896
#define SM_ST 17408
#define SM_STSZ 32768
#define FL_BYTES (SM_ST + 2 * SM_STSZ)   // 82944

__device__ __forceinline__ void load_stage(unsigned st, size_t hb, int jb, int tid) {
    #pragma unroll
    for (int i = 0; i < 16; i++) {
        int e = tid + i * 128;          // 0..2047
        int arr = e >> 10;              // 0:K 1:V
        int x = e & 1023;
        int r = x >> 4, c = x & 15;
        unsigned off = (unsigned)(r * 256 + ((c ^ (r & 7)) << 4));
        const unsigned* src = (arr ? g_v : g_k) + hb + (size_t)(jb + r) * 64 + c * 4;
        cpa16(st + (unsigned)arr * 16384u + off, src);
    }
}

__global__ void __launch_bounds__(128, 2)
flash_mma_kernel(float* __restrict__ out) {
    extern __shared__ unsigned char smem[];
    const unsigned sb0 = (unsigned)__cvta_generic_to_shared(smem);
    unsigned* vbm = (unsigned*)(smem + SM_VB);
    unsigned* sbm = (unsigned*)(smem + SM_SB);

    int bid = blockIdx.x;
    int h   = bid & 7;
    int it  = 63 - (bid >> 3);          // heavy-first, 64-row tile index
    int tid = threadIdx.x, lane = tid & 31, w = tid >> 5;   // w in 0..3
    int g = lane >> 2, t = lane & 3;
    const int qr0 = w * 16;
    const int i0g = it * 64;
    const int iA = i0g + qr0 + g;
    const size_t hb = (size_t)h * SEQ * 64;

    vbm[tid] = g_vbits[h * NW + tid];   // blockDim == NW == 128
    sbm[tid] = g_sbits[h * NW + tid];

    // Q tile (64 rows) + stage 0, one commit group
    #pragma unroll
    for (int i = 0; i < 8; i++) {
        int e = tid + i * 128;          // 0..1023 -> 64 rows x 16 chunks
        int r = e >> 4, c = e & 15;
        unsigned off = (unsigned)(r * 256 + ((c ^ (r & 7)) << 4));
        cpa16(sb0 + SM_Q + off, &g_q[hb + (size_t)(i0g + r) * 64 + c * 4]);
    }
    load_stage(sb0 + SM_ST, hb, 0, tid);
    cpa_commit();
    cpa_wait0();
    __syncthreads();

    int am = (lane >> 3) & 1, ar = lane & 7, ac = lane >> 4;

    // hoisted Q fragments (invariant across jt)
    unsigned Qh[8][4];
    #pragma unroll
    for (int ks = 0; ks < 8; ks++) {
        int row = qr0 + am * 8 + ar, ch = ks * 2 + ac;
        ldsm4(Qh[ks], sb0 + SM_Q + row * 256 + ((ch ^ (row & 7)) << 4));
    }

    float O[16][4];
    #pragma unroll
    for (int o = 0; o < 16; o++) { O[o][0]=0;O[o][1]=0;O[o][2]=0;O[o][3]=0; }
    float lg = 0.f, lg8 = 0.f;

    for (int jt = 0; jt <= it; jt++) {
        if (jt > 0) { cpa_wait0(); __syncthreads(); }
        unsigned st = sb0 + SM_ST + (jt & 1) * SM_STSZ;
        if (jt < it) {
            load_stage(sb0 + SM_ST + ((jt + 1) & 1) * SM_STSZ, hb, (jt + 1) * 64, tid);
            cpa_commit();
        }

        // ---- kt-pipelined QK -> mask/exp -> PV ----
        float Sb[2][2][4];
        int jb = jt * 64;

        // QK for kt = 0
        {
            #pragma unroll
            for (int e = 0; e < 4; e++) { Sb[0][0][e] = 0.f; Sb[0][1][e] = 0.f; }
            #pragma unroll
            for (int ks = 0; ks < 8; ks++) {
                unsigned bh[4];
                int row = am * 8 + ar, ch = ks * 2 + ac;
                ldsm4(bh, st + row * 256 + ((ch ^ (row & 7)) << 4));
                mma16(Sb[0][0], Qh[ks], bh[0], bh[2]);
                mma16(Sb[0][1], Qh[ks], bh[1], bh[3]);
            }
        }

        #pragma unroll
        for (int kt = 0; kt < 4; kt++) {
            int cur = kt & 1, nxt = cur ^ 1;
            if (kt < 3) {
                #pragma unroll
                for (int e = 0; e < 4; e++) { Sb[nxt][0][e] = 0.f; Sb[nxt][1][e] = 0.f; }
                #pragma unroll
                for (int ks = 0; ks < 8; ks++) {
                    unsigned bh[4];
                    int row = (kt + 1) * 16 + am * 8 + ar, ch = ks * 2 + ac;
                    ldsm4(bh, st + row * 256 + ((ch ^ (row & 7)) << 4));
                    mma16(Sb[nxt][0], Qh[ks], bh[0], bh[2]);
                    mma16(Sb[nxt][1], Qh[ks], bh[1], bh[3]);
                }
            }

            // ---- mask + exp for kt ----
            #pragma unroll
            for (int nn = 0; nn < 2; nn++) {
                int n = kt * 2 + nn;
                int cb = n * 8 + 2 * t;
                float* S = Sb[cur][nn];
                #pragma unroll
                for (int e = 0; e < 4; e++) {
                    int roff = (e >> 1) * 8, b = e & 1;
                    int j = jb + cb + b;
                    int d = iA + roff - j;
                    unsigned sbit = (d >= 0) ? ((sbm[d >> 5] >> (d & 31)) & 1u) : 0u;
                    unsigned vbit = (vbm[j >> 5] >> (j & 31)) & 1u;
                    bool ok = (d >= 0) && (vbit || sbit);
                    float p = ok ? __expf(S[e]) : 0.f;
                    p = __half2float(__float2half_rn(p));
                    S[e] = p;
                    if (e < 2) lg += p; else lg8 += p;
                }
            }

            // ---- PV for kt ----
            unsigned aph[4];
            aph[0] = pk2h(Sb[cur][0][0], Sb[cur][0][1]);
            aph[1] = pk2h(Sb[cur][0][2], Sb[cur][0][3]);
            aph[2] = pk2h(Sb[cur][1][0], Sb[cur][1][1]);
            aph[3] = pk2h(Sb[cur][1][2], Sb[cur][1][3]);
            #pragma unroll
            for (int n2 = 0; n2 < 8; n2++) {
                unsigned vh4[4];
                int row = kt * 16 + am * 8 + ar, ch = n2 * 2 + ac;
                ldsm4t(vh4, st + 16384 + row * 256 + ((ch ^ (row & 7)) << 4));
                mma16(O[n2*2],   aph, vh4[0], vh4[1]);
                mma16(O[n2*2+1], aph, vh4[2], vh4[3]);
            }
        }
    }

    // ---- epilogue: per-warp rows, no cross-warp combine ----
    lg  += __shfl_xor_sync(0xffffffffu, lg, 1);  lg  += __shfl_xor_sync(0xffffffffu, lg, 2);
    lg8 += __shfl_xor_sync(0xffffffffu, lg8, 1); lg8 += __shfl_xor_sync(0xffffffffu, lg8, 2);
    float inv0 = 1.0f / lg, inv1 = 1.0f / lg8;
    size_t ob = (size_t)h * SEQ * DH;
    int r0 = i0g + qr0 + g, r1 = r0 + 8;
    #pragma unroll
    for (int o = 0; o < 16; o++) {
        *(float2*)&out[ob + (size_t)r0 * DH + o * 8 + 2 * t] =
            make_float2(O[o][0] * inv0, O[o][1] * inv0);
        *(float2*)&out[ob + (size_t)r1 * DH + o * 8 + 2 * t] =
            make_float2(O[o][2] * inv1, O[o][3] * inv1);
    }
}

// ---------------- launch ----------------
extern "C" void kernel_launch(void* const* d_in, const int* in_sizes, int n_in,
                              void* d_out, int out_size) {
    const float* q = (const float*)d_in[0];
    const float* k = (const float*)d_in[1];
    const float* v = (const float*)d_in[2];
    float* out = (float*)d_out;

    int psm = (64 * QS_STRIDE + 128 * 128) * 4;
    cudaFuncSetAttribute(pattern_kernel, cudaFuncAttributeMaxDynamicSharedMemorySize, psm);
    pattern_kernel<<<dim3(SEQ / 128, NH), 256, psm>>>(q, k, v);
    rowsum_kernel<<<NH * LQ, 128>>>();
    reduce_kernel<<<dim3(NH, SEQ / 128), 128>>>();
    topk_kernel<<<dim3(2, NH), 256>>>();

    cudaFuncSetAttribute(flash_mma_kernel, cudaFuncAttributeMaxDynamicSharedMemorySize, FL_BYTES);
    flash_mma_kernel<<<64 * NH, 128, FL_BYTES>>>(out);
}

// round 15
// speedup vs baseline: 1.3923x; 1.3923x over previous
#include <cuda_runtime.h>
#include <cuda_fp16.h>
#include <math.h>
#include <float.h>

#define NH 8
#define SEQ 4096
#define DH 128
#define LQ 64
#define VTOPK 1024
#define STOPK 2048
#define FORCE_V 30
#define FORCE_S 100
#define SCALE 0.08838834764831845f
#define NW (SEQ / 32)
#define QS_STRIDE 132
#define NPAIR (NH * SEQ * DH / 2)

// ---------------- device scratch ----------------
__device__ float    g_probs[NH * LQ * SEQ];
__device__ float    g_rowinv[NH * LQ];
__device__ float    g_vert [NH * SEQ];
__device__ float    g_slash[NH * SEQ];
__device__ unsigned g_vbits[NH * NW];
__device__ unsigned g_sbits[NH * NW];
// fp16, 2 elems packed per u32 (low = even index)
__device__ unsigned g_q[NPAIR], g_k[NPAIR], g_v[NPAIR];

// ---------------- helpers ----------------
__device__ __forceinline__ void cpa16(unsigned dst, const void* src) {
    asm volatile("cp.async.cg.shared.global [%0], [%1], 16;\n" :: "r"(dst), "l"(src));
}
__device__ __forceinline__ void cpa_commit() { asm volatile("cp.async.commit_group;\n" ::); }
__device__ __forceinline__ void cpa_wait0()  { asm volatile("cp.async.wait_group 0;\n" ::); }

__device__ __forceinline__ void ldsm4(unsigned* r, unsigned a) {
    asm volatile("ldmatrix.sync.aligned.m8n8.x4.shared.b16 {%0,%1,%2,%3}, [%4];"
        : "=r"(r[0]), "=r"(r[1]), "=r"(r[2]), "=r"(r[3]) : "r"(a));
}
__device__ __forceinline__ void ldsm4t(unsigned* r, unsigned a) {
    asm volatile("ldmatrix.sync.aligned.m8n8.x4.trans.shared.b16 {%0,%1,%2,%3}, [%4];"
        : "=r"(r[0]), "=r"(r[1]), "=r"(r[2]), "=r"(r[3]) : "r"(a));
}
__device__ __forceinline__ void mma16(float* d, const unsigned* a, unsigned b0, unsigned b1) {
    asm volatile("mma.sync.aligned.m16n8k16.row.col.f32.f16.f16.f32 "
        "{%0,%1,%2,%3}, {%4,%5,%6,%7}, {%8,%9}, {%0,%1,%2,%3};"
        : "+f"(d[0]), "+f"(d[1]), "+f"(d[2]), "+f"(d[3])
        : "r"(a[0]), "r"(a[1]), "r"(a[2]), "r"(a[3]), "r"(b0), "r"(b1));
}
__device__ __forceinline__ unsigned pk2h(float x, float y) {
    __half2 t = __floats2half2_rn(x, y);
    return *(unsigned*)&t;
}

// ---------------- kernel A: exp-scores for last 64 queries (+ fused fp16 prep) ----------------
__global__ void pattern_kernel(const float* __restrict__ q, const float* __restrict__ k,
                               const float* __restrict__ v) {
    extern __shared__ float psm[];
    float* Qs = psm;
    float* Ks = Qs + 64 * QS_STRIDE;
    int h = blockIdx.y, j0 = blockIdx.x * 128;
    int tid = threadIdx.x, ty = tid >> 4, tx = tid & 15;

    for (int e = tid; e < 64 * 32; e += 256) {
        int r = e >> 5, c = e & 31;
        float4 t = *(const float4*)&q[((size_t)(h * SEQ + SEQ - LQ + r)) * DH + (c << 2)];
        t.x *= SCALE; t.y *= SCALE; t.z *= SCALE; t.w *= SCALE;
        *(float4*)&Qs[r * QS_STRIDE + (c << 2)] = t;
    }
    for (int e = tid; e < 128 * 32; e += 256) {
        int r = e >> 5, c = e & 31;
        *(float4*)&Ks[r * 128 + ((c ^ (r >> 2)) << 2)] =
            *(const float4*)&k[((size_t)(h * SEQ + j0 + r)) * DH + (c << 2)];
    }
    __syncthreads();

    float s[4][8];
    #pragma unroll
    for (int a = 0; a < 4; a++)
        #pragma unroll
        for (int b = 0; b < 8; b++) s[a][b] = 0.f;

    #pragma unroll 4
    for (int c = 0; c < 32; c++) {
        float4 qv[4], kv[8];
        #pragma unroll
        for (int a = 0; a < 4; a++)
            qv[a] = *(const float4*)&Qs[(ty * 4 + a) * QS_STRIDE + (c << 2)];
        #pragma unroll
        for (int b = 0; b < 8; b++) {
            int r = tx * 8 + b;
            kv[b] = *(const float4*)&Ks[r * 128 + ((c ^ (r >> 2)) << 2)];
        }
        #pragma unroll
        for (int a = 0; a < 4; a++)
            #pragma unroll
            for (int b = 0; b < 8; b++)
                s[a][b] += qv[a].x * kv[b].x + qv[a].y * kv[b].y
                         + qv[a].z * kv[b].z + qv[a].w * kv[b].w;
    }
    #pragma unroll
    for (int a = 0; a < 4; a++) {
        int row = ty * 4 + a, qpos = SEQ - LQ + row;
        float p[8];
        #pragma unroll
        for (int b = 0; b < 8; b++) {
            int j = j0 + tx * 8 + b;
            p[b] = (j <= qpos) ? __expf(s[a][b]) : 0.f;
        }
        float* dst = &g_probs[((size_t)(h * LQ + row)) * SEQ + j0 + tx * 8];
        *(float4*)&dst[0] = make_float4(p[0], p[1], p[2], p[3]);
        *(float4*)&dst[4] = make_float4(p[4], p[5], p[6], p[7]);
    }

    // fused fp16 prep (grid-stride over all pairs)
    int gblk = blockIdx.y * gridDim.x + blockIdx.x;          // 0..255
    for (int i = gblk * 256 + tid; i < NPAIR; i += 256 * 256) {
        float2 a = ((const float2*)q)[i];
        g_q[i] = pk2h(a.x * SCALE, a.y * SCALE);
        a = ((const float2*)k)[i];
        g_k[i] = pk2h(a.x, a.y);
        a = ((const float2*)v)[i];
        g_v[i] = pk2h(a.x, a.y);
    }
}

// ---------------- kernel B1: deterministic row sums ----------------
__global__ void rowsum_kernel() {
    int b = blockIdx.x;
    int h = b >> 6, r = b & 63;
    const float* rowp = &g_probs[((size_t)(h * LQ + r)) * SEQ];
    int tid = threadIdx.x;              // 128
    float s = 0.f;
    for (int j = tid; j < SEQ; j += 128) s += rowp[j];
    __shared__ float red[128];
    red[tid] = s; __syncthreads();
    #pragma unroll
    for (int st = 64; st > 0; st >>= 1) {
        if (tid < st) red[tid] += red[tid + st];
        __syncthreads();
    }
    if (tid == 0) g_rowinv[h * LQ + r] = 1.0f / red[0];
}

// ---------------- kernel B2: vertical + slash (z-split for parallelism) ----------------
__global__ void reduce_kernel() {
    int h = blockIdx.x, seg = blockIdx.y, which = blockIdx.z;
    int tid = threadIdx.x;              // 128
    __shared__ float inv[LQ];
    if (tid < LQ) inv[tid] = g_rowinv[h * LQ + tid];
    __syncthreads();
    const float* pb = &g_probs[(size_t)h * LQ * SEQ];
    int j = seg * 128 + tid;
    if (which == 0) {
        float s = 0.f;
        #pragma unroll 8
        for (int lq = 0; lq < LQ; lq++) s += pb[(size_t)lq * SEQ + j] * inv[lq];
        g_vert[h * SEQ + j] = (j < FORCE_V) ? INFINITY : s;
    } else {
        float t = 0.f;
        #pragma unroll 8
        for (int lq = 0; lq < LQ; lq++) {
            int idx = (SEQ - LQ) + lq - j;
            if (idx >= 0) t += pb[(size_t)lq * SEQ + idx] * inv[lq];
        }
        g_slash[h * SEQ + j] = (j < FORCE_S) ? INFINITY : t;
    }
}

// ---------------- kernel C: exact top-k via radix select (warp-shuffle scans) ----------------
__global__ void topk_kernel() {
    int which = blockIdx.x, h = blockIdx.y;
    const float* arr = which ? &g_slash[h * SEQ] : &g_vert[h * SEQ];
    unsigned*   bits = which ? &g_sbits[h * NW]  : &g_vbits[h * NW];
    const int K = which ? STOPK : VTOPK;

    __shared__ unsigned vals[SEQ];
    __shared__ unsigned hist[256];
    __shared__ unsigned wtot[8];
    __shared__ unsigned wpre[4];
    __shared__ int s_b;
    __shared__ unsigned gtw[NW], eqw[NW], wcnt[NW];
    int tid = threadIdx.x;              // 256
    int lane = tid & 31, wp = tid >> 5;

    for (int i = tid; i < SEQ; i += 256) vals[i] = __float_as_uint(arr[i]);
    __syncthreads();

    unsigned prefix = 0; int remaining = K;
    #pragma unroll
    for (int pass = 3; pass >= 0; pass--) {
        int shift = pass * 8;
        hist[tid] = 0u;
        if (tid == 0) s_b = 0;
        __syncthreads();
        unsigned long long ph = (unsigned long long)prefix >> (shift + 8);
        for (int i = tid; i < SEQ; i += 256) {
            unsigned v = vals[i];
            if (((unsigned long long)v >> (shift + 8)) == ph)
                atomicAdd(&hist[(v >> shift) & 255u], 1u);
        }
        __syncthreads();
        // suffix sum over 256 buckets: intra-warp shuffle + cross-warp totals
        unsigned v = hist[tid];
        #pragma unroll
        for (int off = 1; off < 32; off <<= 1) {
            unsigned o = __shfl_down_sync(0xffffffffu, v, off);
            if (lane + off < 32) v += o;
        }
        if (lane == 0) wtot[wp] = v;
        __syncthreads();
        unsigned cross = 0;
        #pragma unroll
        for (int ww = 0; ww < 8; ww++) if (ww > wp) cross += wtot[ww];
        v += cross;
        hist[tid] = v;
        __syncthreads();
        if ((int)hist[tid] >= remaining) atomicMax(&s_b, tid);
        __syncthreads();
        int b = s_b;
        remaining -= (b < 255) ? (int)hist[b + 1] : 0;
        prefix |= ((unsigned)b << shift);
        __syncthreads();
    }

    if (tid < NW) {
        unsigned gm = 0, em = 0;
        #pragma unroll 8
        for (int b = 0; b < 32; b++) {
            unsigned v = vals[tid * 32 + b];
            gm |= (v > prefix ? 1u : 0u) << b;
            em |= (v == prefix ? 1u : 0u) << b;
        }
        gtw[tid] = gm; eqw[tid] = em; wcnt[tid] = __popc(em);
        // intra-warp inclusive prefix
        unsigned v = wcnt[tid];
        #pragma unroll
        for (int off = 1; off < 32; off <<= 1) {
            unsigned o = __shfl_up_sync(0xffffffffu, v, off);
            if (lane >= off) v += o;
        }
        if (lane == 31) wpre[wp] = v;
        eqw[tid] = em;          // keep
        hist[tid] = v;          // reuse hist as scratch for intra-warp inclusive
    }
    __syncthreads();
    if (tid < NW) {
        unsigned cross = 0;
        #pragma unroll
        for (int ww = 0; ww < 4; ww++) if (ww < wp) cross += wpre[ww];
        unsigned incl = hist[tid] + cross;
        unsigned em = eqw[tid], sel = 0;
        int rank = (int)(incl - wcnt[tid]);     // exclusive prefix
        while (em) {
            int b = __ffs(em) - 1;
            if (rank < remaining) sel |= 1u << b;
            rank++;
            em &= em - 1;
        }
        bits[tid] = gtw[tid] | sel;
    }
}

// ---------------- kernel D: tensor-core masked flash attention ----------------
// 128-row q tiles. smem: Q 0..32K, vb@32768, sb@33280,
// stages @34816: each 32K = K(16K) V(16K). total 100352.
#define SM_Q  0
#define SM_VB 32768
#define SM_SB 33280
#define SM_ST 34816
#define SM_STSZ 32768
#define FL_BYTES (SM_ST + 2 * SM_STSZ)

__device__ __forceinline__ void load_stage(unsigned st, size_t hb, int jb, int tid) {
    #pragma unroll
    for (int i = 0; i < 8; i++) {
        int e = tid + i * 256;          // 0..2047
        int arr = e >> 10;              // 0:K 1:V
        int x = e & 1023;
        int r = x >> 4, c = x & 15;
        unsigned off = (unsigned)(r * 256 + ((c ^ (r & 7)) << 4));
        const unsigned* src = (arr ? g_v : g_k) + hb + (size_t)(jb + r) * 64 + c * 4;
        cpa16(st + (unsigned)arr * 16384u + off, src);
    }
}

__global__ void __launch_bounds__(256, 1)
flash_mma_kernel(float* __restrict__ out) {
    extern __shared__ unsigned char smem[];
    const unsigned sb0 = (unsigned)__cvta_generic_to_shared(smem);
    unsigned* vbm = (unsigned*)(smem + SM_VB);
    unsigned* sbm = (unsigned*)(smem + SM_SB);

    int bid = blockIdx.x;
    int h   = bid & 7;
    int itb = 31 - (bid >> 3);          // heavy-first
    int tid = threadIdx.x, lane = tid & 31, w = tid >> 5;
    int g = lane >> 2, t = lane & 3;
    const int qr0 = w * 16;
    const int i0g = itb * 128;
    const int iA = i0g + qr0 + g;
    const int it2 = 2 * itb + 1;
    const size_t hb = (size_t)h * SEQ * 64;

    if (tid < NW)            vbm[tid]      = g_vbits[h * NW + tid];
    else if (tid < 2 * NW)   sbm[tid - NW] = g_sbits[h * NW + tid - NW];

    // Q tile (128 rows) + stage 0, one commit group
    #pragma unroll
    for (int i = 0; i < 8; i++) {
        int e = tid + i * 256;          // 0..2047 -> Q rows
        int r = e >> 4, c = e & 15;
        unsigned off = (unsigned)(r * 256 + ((c ^ (r & 7)) << 4));
        cpa16(sb0 + SM_Q + off, &g_q[hb + (size_t)(i0g + r) * 64 + c * 4]);
    }
    load_stage(sb0 + SM_ST, hb, 0, tid);
    cpa_commit();
    cpa_wait0();
    __syncthreads();

    int am = (lane >> 3) & 1, ar = lane & 7, ac = lane >> 4;

    // hoisted Q fragments (invariant across jt)
    unsigned Qh[8][4];
    #pragma unroll
    for (int ks = 0; ks < 8; ks++) {
        int row = qr0 + am * 8 + ar, ch = ks * 2 + ac;
        ldsm4(Qh[ks], sb0 + SM_Q + row * 256 + ((ch ^ (row & 7)) << 4));
    }

    float O[16][4];
    #pragma unroll
    for (int o = 0; o < 16; o++) { O[o][0]=0;O[o][1]=0;O[o][2]=0;O[o][3]=0; }
    float lg = 0.f, lg8 = 0.f;
    const int ktrot = w & 3;            // per-warp phase stagger

    for (int jt = 0; jt <= it2; jt++) {
        if (jt > 0) { cpa_wait0(); __syncthreads(); }
        unsigned st = sb0 + SM_ST + (jt & 1) * SM_STSZ;
        if (jt < it2) {
            load_stage(sb0 + SM_ST + ((jt + 1) & 1) * SM_STSZ, hb, (jt + 1) * 64, tid);
            cpa_commit();
        }

        int jb = jt * 64;
        // warp-staggered kt order: warps hit MMA/epilogue phases at different times
        #pragma unroll
        for (int kk = 0; kk < 4; kk++) {
            int kt = (kk + ktrot) & 3;

            // ---- QK for this 16-key chunk ----
            float S0[4] = {0.f, 0.f, 0.f, 0.f};
            float S1[4] = {0.f, 0.f, 0.f, 0.f};
            #pragma unroll
            for (int ks = 0; ks < 8; ks++) {
                unsigned bh[4];
                int row = kt * 16 + am * 8 + ar, ch = ks * 2 + ac;
                ldsm4(bh, st + row * 256 + ((ch ^ (row & 7)) << 4));
                mma16(S0, Qh[ks], bh[0], bh[2]);
                mma16(S1, Qh[ks], bh[1], bh[3]);
            }

            // ---- mask + exp (round-9 exact per-element math) ----
            #pragma unroll
            for (int nn = 0; nn < 2; nn++) {
                float* S = nn ? S1 : S0;
                int n = kt * 2 + nn;
                int cb = n * 8 + 2 * t;
                #pragma unroll
                for (int e = 0; e < 4; e++) {
                    int roff = (e >> 1) * 8, b = e & 1;
                    int j = jb + cb + b;
                    int d = iA + roff - j;
                    unsigned sbit = (d >= 0) ? ((sbm[d >> 5] >> (d & 31)) & 1u) : 0u;
                    unsigned vbit = (vbm[j >> 5] >> (j & 31)) & 1u;
                    bool ok = (d >= 0) && (vbit || sbit);
                    float p = ok ? __expf(S[e]) : 0.f;
                    p = __half2float(__float2half_rn(p));
                    S[e] = p;
                    if (e < 2) lg += p; else lg8 += p;
                }
            }

            // ---- PV for this chunk ----
            unsigned aph[4];
            aph[0] = pk2h(S0[0], S0[1]);
            aph[1] = pk2h(S0[2], S0[3]);
            aph[2] = pk2h(S1[0], S1[1]);
            aph[3] = pk2h(S1[2], S1[3]);
            #pragma unroll
            for (int n2 = 0; n2 < 8; n2++) {
                unsigned vh4[4];
                int row = kt * 16 + am * 8 + ar, ch = n2 * 2 + ac;
                ldsm4t(vh4, st + 16384 + row * 256 + ((ch ^ (row & 7)) << 4));
                mma16(O[n2*2],   aph, vh4[0], vh4[1]);
                mma16(O[n2*2+1], aph, vh4[2], vh4[3]);
            }
        }
    }

    // ---- epilogue: per-warp rows, no cross-warp combine ----
    lg  += __shfl_xor_sync(0xffffffffu, lg, 1);  lg  += __shfl_xor_sync(0xffffffffu, lg, 2);
    lg8 += __shfl_xor_sync(0xffffffffu, lg8, 1); lg8 += __shfl_xor_sync(0xffffffffu, lg8, 2);
    float inv0 = 1.0f / lg, inv1 = 1.0f / lg8;
    size_t ob = (size_t)h * SEQ * DH;
    int r0 = i0g + qr0 + g, r1 = r0 + 8;
    #pragma unroll
    for (int o = 0; o < 16; o++) {
        *(float2*)&out[ob + (size_t)r0 * DH + o * 8 + 2 * t] =
            make_float2(O[o][0] * inv0, O[o][1] * inv0);
        *(float2*)&out[ob + (size_t)r1 * DH + o * 8 + 2 * t] =
            make_float2(O[o][2] * inv1, O[o][3] * inv1);
    }
}

// ---------------- launch ----------------
extern "C" void kernel_launch(void* const* d_in, const int* in_sizes, int n_in,
                              void* d_out, int out_size) {
    const float* q = (const float*)d_in[0];
    const float* k = (const float*)d_in[1];
    const float* v = (const float*)d_in[2];
    float* out = (float*)d_out;

    int psm = (64 * QS_STRIDE + 128 * 128) * 4;
    cudaFuncSetAttribute(pattern_kernel, cudaFuncAttributeMaxDynamicSharedMemorySize, psm);
    pattern_kernel<<<dim3(SEQ / 128, NH), 256, psm>>>(q, k, v);
    rowsum_kernel<<<NH * LQ, 128>>>();
    reduce_kernel<<<dim3(NH, SEQ / 128, 2), 128>>>();
    topk_kernel<<<dim3(2, NH), 256>>>();

    cudaFuncSetAttribute(flash_mma_kernel, cudaFuncAttributeMaxDynamicSharedMemorySize, FL_BYTES);
    flash_mma_kernel<<<32 * NH, 256, FL_BYTES>>>(out);
}

// round 16
// speedup vs baseline: 1.7823x; 1.2802x over previous
#include <cuda_runtime.h>
#include <cuda_fp16.h>
#include <math.h>
#include <float.h>

#define NH 8
#define SEQ 4096
#define DH 128
#define LQ 64
#define VTOPK 1024
#define STOPK 2048
#define FORCE_V 30
#define FORCE_S 100
#define SCALE 0.08838834764831845f
#define SCALE2 0.12751743360424452f   // SCALE * log2(e)
#define NW (SEQ / 32)
#define QS_STRIDE 132
#define NPAIR (NH * SEQ * DH / 2)

// ---------------- device scratch ----------------
__device__ float    g_probs[NH * LQ * SEQ];
__device__ unsigned g_vbits[NH * NW];
__device__ unsigned g_sbits[NH * NW];
// fp16, 2 elems packed per u32 (low = even index)
__device__ unsigned g_q[NPAIR], g_k[NPAIR], g_v[NPAIR];

// ---------------- helpers ----------------
__device__ __forceinline__ void cpa16(unsigned dst, const void* src) {
    asm volatile("cp.async.cg.shared.global [%0], [%1], 16;\n" :: "r"(dst), "l"(src));
}
__device__ __forceinline__ void cpa_commit() { asm volatile("cp.async.commit_group;\n" ::); }
__device__ __forceinline__ void cpa_wait0()  { asm volatile("cp.async.wait_group 0;\n" ::); }

__device__ __forceinline__ void ldsm4(unsigned* r, unsigned a) {
    asm volatile("ldmatrix.sync.aligned.m8n8.x4.shared.b16 {%0,%1,%2,%3}, [%4];"
        : "=r"(r[0]), "=r"(r[1]), "=r"(r[2]), "=r"(r[3]) : "r"(a));
}
__device__ __forceinline__ void ldsm4t(unsigned* r, unsigned a) {
    asm volatile("ldmatrix.sync.aligned.m8n8.x4.trans.shared.b16 {%0,%1,%2,%3}, [%4];"
        : "=r"(r[0]), "=r"(r[1]), "=r"(r[2]), "=r"(r[3]) : "r"(a));
}
__device__ __forceinline__ void mma16(float* d, const unsigned* a, unsigned b0, unsigned b1) {
    asm volatile("mma.sync.aligned.m16n8k16.row.col.f32.f16.f16.f32 "
        "{%0,%1,%2,%3}, {%4,%5,%6,%7}, {%8,%9}, {%0,%1,%2,%3};"
        : "+f"(d[0]), "+f"(d[1]), "+f"(d[2]), "+f"(d[3])
        : "r"(a[0]), "r"(a[1]), "r"(a[2]), "r"(a[3]), "r"(b0), "r"(b1));
}
__device__ __forceinline__ unsigned pk2h(float x, float y) {
    __half2 t = __floats2half2_rn(x, y);
    return *(unsigned*)&t;
}

// ---------------- kernel A: exp-scores for last 64 queries (+ fused fp16 prep) ----------------
__global__ void pattern_kernel(const float* __restrict__ q, const float* __restrict__ k,
                               const float* __restrict__ v) {
    extern __shared__ float psm[];
    float* Qs = psm;
    float* Ks = Qs + 64 * QS_STRIDE;
    int h = blockIdx.y, j0 = blockIdx.x * 128;
    int tid = threadIdx.x, ty = tid >> 4, tx = tid & 15;

    for (int e = tid; e < 64 * 32; e += 256) {
        int r = e >> 5, c = e & 31;
        float4 t = *(const float4*)&q[((size_t)(h * SEQ + SEQ - LQ + r)) * DH + (c << 2)];
        t.x *= SCALE; t.y *= SCALE; t.z *= SCALE; t.w *= SCALE;
        *(float4*)&Qs[r * QS_STRIDE + (c << 2)] = t;
    }
    for (int e = tid; e < 128 * 32; e += 256) {
        int r = e >> 5, c = e & 31;
        *(float4*)&Ks[r * 128 + ((c ^ (r >> 2)) << 2)] =
            *(const float4*)&k[((size_t)(h * SEQ + j0 + r)) * DH + (c << 2)];
    }
    __syncthreads();

    float s[4][8];
    #pragma unroll
    for (int a = 0; a < 4; a++)
        #pragma unroll
        for (int b = 0; b < 8; b++) s[a][b] = 0.f;

    #pragma unroll 4
    for (int c = 0; c < 32; c++) {
        float4 qv[4], kv[8];
        #pragma unroll
        for (int a = 0; a < 4; a++)
            qv[a] = *(const float4*)&Qs[(ty * 4 + a) * QS_STRIDE + (c << 2)];
        #pragma unroll
        for (int b = 0; b < 8; b++) {
            int r = tx * 8 + b;
            kv[b] = *(const float4*)&Ks[r * 128 + ((c ^ (r >> 2)) << 2)];
        }
        #pragma unroll
        for (int a = 0; a < 4; a++)
            #pragma unroll
            for (int b = 0; b < 8; b++)
                s[a][b] += qv[a].x * kv[b].x + qv[a].y * kv[b].y
                         + qv[a].z * kv[b].z + qv[a].w * kv[b].w;
    }
    #pragma unroll
    for (int a = 0; a < 4; a++) {
        int row = ty * 4 + a, qpos = SEQ - LQ + row;
        float p[8];
        #pragma unroll
        for (int b = 0; b < 8; b++) {
            int j = j0 + tx * 8 + b;
            p[b] = (j <= qpos) ? __expf(s[a][b]) : 0.f;
        }
        float* dst = &g_probs[((size_t)(h * LQ + row)) * SEQ + j0 + tx * 8];
        *(float4*)&dst[0] = make_float4(p[0], p[1], p[2], p[3]);
        *(float4*)&dst[4] = make_float4(p[4], p[5], p[6], p[7]);
    }

    // fused fp16 prep (grid-stride over all pairs); q scaled by SCALE*log2(e)
    int gblk = blockIdx.y * gridDim.x + blockIdx.x;          // 0..255
    for (int i = gblk * 256 + tid; i < NPAIR; i += 256 * 256) {
        float2 a = ((const float2*)q)[i];
        g_q[i] = pk2h(a.x * SCALE2, a.y * SCALE2);
        a = ((const float2*)k)[i];
        g_k[i] = pk2h(a.x, a.y);
        a = ((const float2*)v)[i];
        g_v[i] = pk2h(a.x, a.y);
    }
}

// ---------------- kernel B: fused rowsum + vert/slash + exact top-k ----------------
// grid (2, NH), 1024 threads. Masks bit-identical to the previous 3-kernel chain.
__global__ void select_kernel() {
    int which = blockIdx.x, h = blockIdx.y;
    unsigned* bits = which ? &g_sbits[h * NW] : &g_vbits[h * NW];
    const int K = which ? STOPK : VTOPK;
    const int FORCE = which ? FORCE_S : FORCE_V;

    __shared__ float inv[LQ];
    __shared__ float red[8][128];
    __shared__ float vals_f[SEQ];       // 16 KB
    __shared__ unsigned hist[256];
    __shared__ unsigned wtot[8];
    __shared__ unsigned wpre[4];
    __shared__ int s_b;
    __shared__ unsigned gtw[NW], eqw[NW], wcnt[NW], iwp[NW];

    int tid = threadIdx.x;              // 1024
    int lane = tid & 31, wp = tid >> 5;
    const float* pb = &g_probs[(size_t)h * LQ * SEQ];

    // ---- phase 1: row sums, order identical to old rowsum_kernel ----
    {
        int rg = tid >> 7;              // row-group 0..7
        int rt = tid & 127;
        #pragma unroll 1
        for (int pass = 0; pass < 8; pass++) {
            int r = pass * 8 + rg;
            const float* rowp = pb + (size_t)r * SEQ;
            float s = 0.f;
            for (int j = rt; j < SEQ; j += 128) s += rowp[j];
            red[rg][rt] = s; __syncthreads();
            #pragma unroll
            for (int st = 64; st > 0; st >>= 1) {
                if (rt < st) red[rg][rt] += red[rg][rt + st];
                __syncthreads();
            }
            if (rt == 0) inv[r] = 1.0f / red[rg][0];
            __syncthreads();
        }
    }

    // ---- phase 2: vertical / slash scores into smem (element order unchanged) ----
    if (which == 0) {
        for (int j = tid; j < SEQ; j += 1024) {
            float s = 0.f;
            #pragma unroll 8
            for (int lq = 0; lq < LQ; lq++) s += pb[(size_t)lq * SEQ + j] * inv[lq];
            vals_f[j] = (j < FORCE) ? INFINITY : s;
        }
    } else {
        for (int j = tid; j < SEQ; j += 1024) {
            float t2 = 0.f;
            #pragma unroll 8
            for (int lq = 0; lq < LQ; lq++) {
                int idx = (SEQ - LQ) + lq - j;
                if (idx >= 0) t2 += pb[(size_t)lq * SEQ + idx] * inv[lq];
            }
            vals_f[j] = (j < FORCE) ? INFINITY : t2;
        }
    }
    __syncthreads();

    // ---- phase 3: radix select (same semantics as before) ----
    unsigned prefix = 0; int remaining = K;
    #pragma unroll 1
    for (int pass = 3; pass >= 0; pass--) {
        int shift = pass * 8;
        if (tid < 256) hist[tid] = 0u;
        if (tid == 0) s_b = 0;
        __syncthreads();
        unsigned long long ph = (unsigned long long)prefix >> (shift + 8);
        for (int i = tid; i < SEQ; i += 1024) {
            unsigned v = __float_as_uint(vals_f[i]);
            if (((unsigned long long)v >> (shift + 8)) == ph)
                atomicAdd(&hist[(v >> shift) & 255u], 1u);
        }
        __syncthreads();
        unsigned v = 0;
        if (tid < 256) {
            v = hist[tid];
            #pragma unroll
            for (int off = 1; off < 32; off <<= 1) {
                unsigned o = __shfl_down_sync(0xffffffffu, v, off);
                if (lane + off < 32) v += o;
            }
            if (lane == 0) wtot[wp] = v;
        }
        __syncthreads();
        if (tid < 256) {
            unsigned cross = 0;
            #pragma unroll
            for (int ww = 0; ww < 8; ww++) if (ww > wp) cross += wtot[ww];
            hist[tid] = v + cross;      // suffix sum
        }
        __syncthreads();
        if (tid < 256 && (int)hist[tid] >= remaining) atomicMax(&s_b, tid);
        __syncthreads();
        int b = s_b;
        remaining -= (b < 255) ? (int)hist[b + 1] : 0;
        prefix |= ((unsigned)b << shift);
        __syncthreads();
    }

    if (tid < NW) {
        unsigned gm = 0, em = 0;
        #pragma unroll 8
        for (int b = 0; b < 32; b++) {
            unsigned v = __float_as_uint(vals_f[tid * 32 + b]);
            gm |= (v > prefix ? 1u : 0u) << b;
            em |= (v == prefix ? 1u : 0u) << b;
        }
        gtw[tid] = gm; eqw[tid] = em; wcnt[tid] = __popc(em);
        unsigned v = __popc(em);
        #pragma unroll
        for (int off = 1; off < 32; off <<= 1) {
            unsigned o = __shfl_up_sync(0xffffffffu, v, off);
            if (lane >= off) v += o;
        }
        if (lane == 31) wpre[wp] = v;
        iwp[tid] = v;
    }
    __syncthreads();
    if (tid < NW) {
        unsigned cross = 0;
        #pragma unroll
        for (int ww = 0; ww < 4; ww++) if (ww < wp) cross += wpre[ww];
        unsigned incl = iwp[tid] + cross;
        unsigned em = eqw[tid], sel = 0;
        int rank = (int)(incl - wcnt[tid]);
        while (em) {
            int b = __ffs(em) - 1;
            if (rank < remaining) sel |= 1u << b;
            rank++;
            em &= em - 1;
        }
        bits[tid] = gtw[tid] | sel;
    }
}

// ---------------- kernel C: tensor-core masked flash attention ----------------
// 128-row q tiles. smem: Q 0..32K, vb@32768, sb@33280,
// stages @34816: each 32K = K(16K) V(16K). total 100352.
#define SM_Q  0
#define SM_VB 32768
#define SM_SB 33280
#define SM_ST 34816
#define SM_STSZ 32768
#define FL_BYTES (SM_ST + 2 * SM_STSZ)

__device__ __forceinline__ void load_stage(unsigned st, size_t hb, int jb, int tid) {
    #pragma unroll
    for (int i = 0; i < 8; i++) {
        int e = tid + i * 256;          // 0..2047
        int arr = e >> 10;              // 0:K 1:V
        int x = e & 1023;
        int r = x >> 4, c = x & 15;
        unsigned off = (unsigned)(r * 256 + ((c ^ (r & 7)) << 4));
        const unsigned* src = (arr ? g_v : g_k) + hb + (size_t)(jb + r) * 64 + c * 4;
        cpa16(st + (unsigned)arr * 16384u + off, src);
    }
}

__global__ void __launch_bounds__(256, 1)
flash_mma_kernel(float* __restrict__ out) {
    extern __shared__ unsigned char smem[];
    const unsigned sb0 = (unsigned)__cvta_generic_to_shared(smem);
    unsigned* vbm = (unsigned*)(smem + SM_VB);
    unsigned* sbm = (unsigned*)(smem + SM_SB);

    int bid = blockIdx.x;
    int h   = bid & 7;
    int itb = 31 - (bid >> 3);          // heavy-first
    int tid = threadIdx.x, lane = tid & 31, w = tid >> 5;
    int g = lane >> 2, t = lane & 3;
    const int qr0 = w * 16;
    const int i0g = itb * 128;
    const int iA = i0g + qr0 + g;
    const int it2 = 2 * itb + 1;
    const size_t hb = (size_t)h * SEQ * 64;

    if (tid < NW)            vbm[tid]      = g_vbits[h * NW + tid];
    else if (tid < 2 * NW)   sbm[tid - NW] = g_sbits[h * NW + tid - NW];

    // Q tile (128 rows) + stage 0, one commit group
    #pragma unroll
    for (int i = 0; i < 8; i++) {
        int e = tid + i * 256;          // 0..2047 -> Q rows
        int r = e >> 4, c = e & 15;
        unsigned off = (unsigned)(r * 256 + ((c ^ (r & 7)) << 4));
        cpa16(sb0 + SM_Q + off, &g_q[hb + (size_t)(i0g + r) * 64 + c * 4]);
    }
    load_stage(sb0 + SM_ST, hb, 0, tid);
    cpa_commit();
    cpa_wait0();
    __syncthreads();

    int am = (lane >> 3) & 1, ar = lane & 7, ac = lane >> 4;

    // hoisted Q fragments (invariant across jt)
    unsigned Qh[8][4];
    #pragma unroll
    for (int ks = 0; ks < 8; ks++) {
        int row = qr0 + am * 8 + ar, ch = ks * 2 + ac;
        ldsm4(Qh[ks], sb0 + SM_Q + row * 256 + ((ch ^ (row & 7)) << 4));
    }

    float O[16][4];
    #pragma unroll
    for (int o = 0; o < 16; o++) { O[o][0]=0;O[o][1]=0;O[o][2]=0;O[o][3]=0; }
    float lg = 0.f, lg8 = 0.f;
    const int ktrot = w & 3;            // per-warp phase stagger

    for (int jt = 0; jt <= it2; jt++) {
        if (jt > 0) { cpa_wait0(); __syncthreads(); }
        unsigned st = sb0 + SM_ST + (jt & 1) * SM_STSZ;
        if (jt < it2) {
            load_stage(sb0 + SM_ST + ((jt + 1) & 1) * SM_STSZ, hb, (jt + 1) * 64, tid);
            cpa_commit();
        }

        int jb = jt * 64;
        #pragma unroll
        for (int kk = 0; kk < 4; kk++) {
            int kt = (kk + ktrot) & 3;

            // ---- QK for this 16-key chunk ----
            float S0[4] = {0.f, 0.f, 0.f, 0.f};
            float S1[4] = {0.f, 0.f, 0.f, 0.f};
            #pragma unroll
            for (int ks = 0; ks < 8; ks++) {
                unsigned bh[4];
                int row = kt * 16 + am * 8 + ar, ch = ks * 2 + ac;
                ldsm4(bh, st + row * 256 + ((ch ^ (row & 7)) << 4));
                mma16(S0, Qh[ks], bh[0], bh[2]);
                mma16(S1, Qh[ks], bh[1], bh[3]);
            }

            // ---- mask + ex2 + single-pack epilogue ----
            unsigned aph[4];
            #pragma unroll
            for (int nn = 0; nn < 2; nn++) {
                float* S = nn ? S1 : S0;
                int n = kt * 2 + nn;
                int cb = n * 8 + 2 * t;
                #pragma unroll
                for (int e = 0; e < 4; e++) {
                    int roff = (e >> 1) * 8, b = e & 1;
                    int j = jb + cb + b;
                    int d = iA + roff - j;
                    unsigned sbit = (d >= 0) ? ((sbm[d >> 5] >> (d & 31)) & 1u) : 0u;
                    unsigned vbit = (vbm[j >> 5] >> (j & 31)) & 1u;
                    bool ok = (d >= 0) && (vbit || sbit);
                    float p;
                    asm("ex2.approx.ftz.f32 %0, %1;" : "=f"(p) : "f"(S[e]));
                    S[e] = ok ? p : 0.f;
                }
                __half2 hA = __floats2half2_rn(S[0], S[1]);
                __half2 hB = __floats2half2_rn(S[2], S[3]);
                float2 fA = __half22float2(hA);
                float2 fB = __half22float2(hB);
                lg  += fA.x + fA.y;
                lg8 += fB.x + fB.y;
                aph[nn * 2 + 0] = *(unsigned*)&hA;
                aph[nn * 2 + 1] = *(unsigned*)&hB;
            }

            // ---- PV for this chunk ----
            #pragma unroll
            for (int n2 = 0; n2 < 8; n2++) {
                unsigned vh4[4];
                int row = kt * 16 + am * 8 + ar, ch = n2 * 2 + ac;
                ldsm4t(vh4, st + 16384 + row * 256 + ((ch ^ (row & 7)) << 4));
                mma16(O[n2*2],   aph, vh4[0], vh4[1]);
                mma16(O[n2*2+1], aph, vh4[2], vh4[3]);
            }
        }
    }

    // ---- epilogue: per-warp rows, no cross-warp combine ----
    lg  += __shfl_xor_sync(0xffffffffu, lg, 1);  lg  += __shfl_xor_sync(0xffffffffu, lg, 2);
    lg8 += __shfl_xor_sync(0xffffffffu, lg8, 1); lg8 += __shfl_xor_sync(0xffffffffu, lg8, 2);
    float inv0 = 1.0f / lg, inv1 = 1.0f / lg8;
    size_t ob = (size_t)h * SEQ * DH;
    int r0 = i0g + qr0 + g, r1 = r0 + 8;
    #pragma unroll
    for (int o = 0; o < 16; o++) {
        *(float2*)&out[ob + (size_t)r0 * DH + o * 8 + 2 * t] =
            make_float2(O[o][0] * inv0, O[o][1] * inv0);
        *(float2*)&out[ob + (size_t)r1 * DH + o * 8 + 2 * t] =
            make_float2(O[o][2] * inv1, O[o][3] * inv1);
    }
}

// ---------------- launch ----------------
extern "C" void kernel_launch(void* const* d_in, const int* in_sizes, int n_in,
                              void* d_out, int out_size) {
    const float* q = (const float*)d_in[0];
    const float* k = (const float*)d_in[1];
    const float* v = (const float*)d_in[2];
    float* out = (float*)d_out;

    int psm = (64 * QS_STRIDE + 128 * 128) * 4;
    cudaFuncSetAttribute(pattern_kernel, cudaFuncAttributeMaxDynamicSharedMemorySize, psm);
    pattern_kernel<<<dim3(SEQ / 128, NH), 256, psm>>>(q, k, v);
    select_kernel<<<dim3(2, NH), 1024>>>();

    cudaFuncSetAttribute(flash_mma_kernel, cudaFuncAttributeMaxDynamicSharedMemorySize, FL_BYTES);
    flash_mma_kernel<<<32 * NH, 256, FL_BYTES>>>(out);
}

// round 17
// speedup vs baseline: 2.0520x; 1.1513x over previous
#include <cuda_runtime.h>
#include <cuda_fp16.h>
#include <math.h>
#include <float.h>

#define NH 8
#define SEQ 4096
#define DH 128
#define LQ 64
#define VTOPK 1024
#define STOPK 2048
#define FORCE_V 30
#define FORCE_S 100
#define SCALE 0.08838834764831845f
#define SCALE2 0.12751743360424452f   // SCALE * log2(e)
#define NW (SEQ / 32)
#define QS_STRIDE 132
#define NPAIR (NH * SEQ * DH / 2)

// ---------------- device scratch ----------------
__device__ float    g_probs[NH * LQ * SEQ];
__device__ unsigned g_vbits[NH * NW];
__device__ unsigned g_sbits[NH * NW];
// fp16, 2 elems packed per u32 (low = even index)
__device__ unsigned g_q[NPAIR], g_k[NPAIR], g_v[NPAIR];

// ---------------- helpers ----------------
__device__ __forceinline__ void cpa16(unsigned dst, const void* src) {
    asm volatile("cp.async.cg.shared.global [%0], [%1], 16;\n" :: "r"(dst), "l"(src));
}
__device__ __forceinline__ void cpa_commit() { asm volatile("cp.async.commit_group;\n" ::); }
__device__ __forceinline__ void cpa_wait0()  { asm volatile("cp.async.wait_group 0;\n" ::); }

__device__ __forceinline__ void ldsm4(unsigned* r, unsigned a) {
    asm volatile("ldmatrix.sync.aligned.m8n8.x4.shared.b16 {%0,%1,%2,%3}, [%4];"
        : "=r"(r[0]), "=r"(r[1]), "=r"(r[2]), "=r"(r[3]) : "r"(a));
}
__device__ __forceinline__ void ldsm4t(unsigned* r, unsigned a) {
    asm volatile("ldmatrix.sync.aligned.m8n8.x4.trans.shared.b16 {%0,%1,%2,%3}, [%4];"
        : "=r"(r[0]), "=r"(r[1]), "=r"(r[2]), "=r"(r[3]) : "r"(a));
}
__device__ __forceinline__ void mma16(float* d, const unsigned* a, unsigned b0, unsigned b1) {
    asm volatile("mma.sync.aligned.m16n8k16.row.col.f32.f16.f16.f32 "
        "{%0,%1,%2,%3}, {%4,%5,%6,%7}, {%8,%9}, {%0,%1,%2,%3};"
        : "+f"(d[0]), "+f"(d[1]), "+f"(d[2]), "+f"(d[3])
        : "r"(a[0]), "r"(a[1]), "r"(a[2]), "r"(a[3]), "r"(b0), "r"(b1));
}
__device__ __forceinline__ unsigned pk2h(float x, float y) {
    __half2 t = __floats2half2_rn(x, y);
    return *(unsigned*)&t;
}

// allow words for one query row: local key cols 0..63 of a 64-key tile.
// D = row - jb. sbm must be zero-padded to >= NW+2 words.
__device__ __forceinline__ void build_allow(int D, const unsigned* sbm,
                                            unsigned vlo, unsigned vhi,
                                            unsigned& alo, unsigned& ahi) {
    if (D < 0) { alo = 0u; ahi = 0u; return; }
    unsigned clo = (D >= 31) ? 0xffffffffu : ((2u << D) - 1u);
    unsigned chi = (D >= 63) ? 0xffffffffu : ((D >= 32) ? ((2u << (D - 32)) - 1u) : 0u);
    unsigned rlo, rhi;
    int ls = D - 31;
    if (ls >= 0) rlo = __brev(__funnelshift_r(sbm[ls >> 5], sbm[(ls >> 5) + 1], ls & 31));
    else         rlo = __brev(sbm[0] << (31 - D));
    int hs = D - 63;
    if (hs >= 0)      rhi = __brev(__funnelshift_r(sbm[hs >> 5], sbm[(hs >> 5) + 1], hs & 31));
    else if (D >= 32) rhi = __brev(sbm[0] << (63 - D));
    else              rhi = 0u;
    alo = (vlo | rlo) & clo;
    ahi = (vhi | rhi) & chi;
}

// ---------------- kernel A: exp-scores for last 64 queries (+ fused fp16 prep) ----------------
// K tile = 64 keys -> grid (64, NH), smem 66.5 KB -> 3 CTAs/SM.
__global__ void pattern_kernel(const float* __restrict__ q, const float* __restrict__ k,
                               const float* __restrict__ v) {
    extern __shared__ float psm[];
    float* Qs = psm;                     // [64][132]
    float* Ks = Qs + 64 * QS_STRIDE;     // [64][128] swizzled
    int h = blockIdx.y, j0 = blockIdx.x * 64;
    int tid = threadIdx.x, ty = tid >> 4, tx = tid & 15;

    for (int e = tid; e < 64 * 32; e += 256) {
        int r = e >> 5, c = e & 31;
        float4 t = *(const float4*)&q[((size_t)(h * SEQ + SEQ - LQ + r)) * DH + (c << 2)];
        t.x *= SCALE; t.y *= SCALE; t.z *= SCALE; t.w *= SCALE;
        *(float4*)&Qs[r * QS_STRIDE + (c << 2)] = t;
    }
    for (int e = tid; e < 64 * 32; e += 256) {
        int r = e >> 5, c = e & 31;
        *(float4*)&Ks[r * 128 + ((c ^ (r >> 2)) << 2)] =
            *(const float4*)&k[((size_t)(h * SEQ + j0 + r)) * DH + (c << 2)];
    }
    __syncthreads();

    float s[4][4];
    #pragma unroll
    for (int a = 0; a < 4; a++)
        #pragma unroll
        for (int b = 0; b < 4; b++) s[a][b] = 0.f;

    #pragma unroll 4
    for (int c = 0; c < 32; c++) {
        float4 qv[4], kv[4];
        #pragma unroll
        for (int a = 0; a < 4; a++)
            qv[a] = *(const float4*)&Qs[(ty * 4 + a) * QS_STRIDE + (c << 2)];
        #pragma unroll
        for (int b = 0; b < 4; b++) {
            int r = tx * 4 + b;
            kv[b] = *(const float4*)&Ks[r * 128 + ((c ^ (r >> 2)) << 2)];
        }
        #pragma unroll
        for (int a = 0; a < 4; a++)
            #pragma unroll
            for (int b = 0; b < 4; b++)
                s[a][b] += qv[a].x * kv[b].x + qv[a].y * kv[b].y
                         + qv[a].z * kv[b].z + qv[a].w * kv[b].w;
    }
    #pragma unroll
    for (int a = 0; a < 4; a++) {
        int row = ty * 4 + a, qpos = SEQ - LQ + row;
        float p[4];
        #pragma unroll
        for (int b = 0; b < 4; b++) {
            int j = j0 + tx * 4 + b;
            p[b] = (j <= qpos) ? __expf(s[a][b]) : 0.f;
        }
        float* dst = &g_probs[((size_t)(h * LQ + row)) * SEQ + j0 + tx * 4];
        *(float4*)&dst[0] = make_float4(p[0], p[1], p[2], p[3]);
    }

    // fused fp16 prep (grid-stride over all pairs); q scaled by SCALE*log2(e)
    int gblk = blockIdx.y * gridDim.x + blockIdx.x;          // 0..511
    for (int i = gblk * 256 + tid; i < NPAIR; i += 512 * 256) {
        float2 a = ((const float2*)q)[i];
        g_q[i] = pk2h(a.x * SCALE2, a.y * SCALE2);
        a = ((const float2*)k)[i];
        g_k[i] = pk2h(a.x, a.y);
        a = ((const float2*)v)[i];
        g_v[i] = pk2h(a.x, a.y);
    }
}

// ---------------- kernel B: fused rowsum + vert/slash + exact top-k ----------------
__global__ void select_kernel() {
    int which = blockIdx.x, h = blockIdx.y;
    unsigned* bits = which ? &g_sbits[h * NW] : &g_vbits[h * NW];
    const int K = which ? STOPK : VTOPK;
    const int FORCE = which ? FORCE_S : FORCE_V;

    __shared__ float inv[LQ];
    __shared__ float red[8][128];
    __shared__ float vals_f[SEQ];
    __shared__ unsigned hist[256];
    __shared__ unsigned wtot[8];
    __shared__ unsigned wpre[4];
    __shared__ int s_b;
    __shared__ unsigned gtw[NW], eqw[NW], wcnt[NW], iwp[NW];

    int tid = threadIdx.x;              // 1024
    int lane = tid & 31, wp = tid >> 5;
    const float* pb = &g_probs[(size_t)h * LQ * SEQ];

    // ---- phase 1: row sums (order identical to old rowsum_kernel) ----
    {
        int rg = tid >> 7;
        int rt = tid & 127;
        #pragma unroll 1
        for (int pass = 0; pass < 8; pass++) {
            int r = pass * 8 + rg;
            const float* rowp = pb + (size_t)r * SEQ;
            float s = 0.f;
            for (int j = rt; j < SEQ; j += 128) s += rowp[j];
            red[rg][rt] = s; __syncthreads();
            #pragma unroll
            for (int st = 64; st > 0; st >>= 1) {
                if (rt < st) red[rg][rt] += red[rg][rt + st];
                __syncthreads();
            }
            if (rt == 0) inv[r] = 1.0f / red[rg][0];
            __syncthreads();
        }
    }

    // ---- phase 2: vertical / slash scores ----
    if (which == 0) {
        for (int j = tid; j < SEQ; j += 1024) {
            float s = 0.f;
            #pragma unroll 8
            for (int lq = 0; lq < LQ; lq++) s += pb[(size_t)lq * SEQ + j] * inv[lq];
            vals_f[j] = (j < FORCE) ? INFINITY : s;
        }
    } else {
        for (int j = tid; j < SEQ; j += 1024) {
            float t2 = 0.f;
            #pragma unroll 8
            for (int lq = 0; lq < LQ; lq++) {
                int idx = (SEQ - LQ) + lq - j;
                if (idx >= 0) t2 += pb[(size_t)lq * SEQ + idx] * inv[lq];
            }
            vals_f[j] = (j < FORCE) ? INFINITY : t2;
        }
    }
    __syncthreads();

    // ---- phase 3: radix select ----
    unsigned prefix = 0; int remaining = K;
    #pragma unroll 1
    for (int pass = 3; pass >= 0; pass--) {
        int shift = pass * 8;
        if (tid < 256) hist[tid] = 0u;
        if (tid == 0) s_b = 0;
        __syncthreads();
        unsigned long long ph = (unsigned long long)prefix >> (shift + 8);
        for (int i = tid; i < SEQ; i += 1024) {
            unsigned v = __float_as_uint(vals_f[i]);
            if (((unsigned long long)v >> (shift + 8)) == ph)
                atomicAdd(&hist[(v >> shift) & 255u], 1u);
        }
        __syncthreads();
        unsigned v = 0;
        if (tid < 256) {
            v = hist[tid];
            #pragma unroll
            for (int off = 1; off < 32; off <<= 1) {
                unsigned o = __shfl_down_sync(0xffffffffu, v, off);
                if (lane + off < 32) v += o;
            }
            if (lane == 0) wtot[wp] = v;
        }
        __syncthreads();
        if (tid < 256) {
            unsigned cross = 0;
            #pragma unroll
            for (int ww = 0; ww < 8; ww++) if (ww > wp) cross += wtot[ww];
            hist[tid] = v + cross;
        }
        __syncthreads();
        if (tid < 256 && (int)hist[tid] >= remaining) atomicMax(&s_b, tid);
        __syncthreads();
        int b = s_b;
        remaining -= (b < 255) ? (int)hist[b + 1] : 0;
        prefix |= ((unsigned)b << shift);
        __syncthreads();
    }

    if (tid < NW) {
        unsigned gm = 0, em = 0;
        #pragma unroll 8
        for (int b = 0; b < 32; b++) {
            unsigned v = __float_as_uint(vals_f[tid * 32 + b]);
            gm |= (v > prefix ? 1u : 0u) << b;
            em |= (v == prefix ? 1u : 0u) << b;
        }
        gtw[tid] = gm; eqw[tid] = em; wcnt[tid] = __popc(em);
        unsigned v = __popc(em);
        #pragma unroll
        for (int off = 1; off < 32; off <<= 1) {
            unsigned o = __shfl_up_sync(0xffffffffu, v, off);
            if (lane >= off) v += o;
        }
        if (lane == 31) wpre[wp] = v;
        iwp[tid] = v;
    }
    __syncthreads();
    if (tid < NW) {
        unsigned cross = 0;
        #pragma unroll
        for (int ww = 0; ww < 4; ww++) if (ww < wp) cross += wpre[ww];
        unsigned incl = iwp[tid] + cross;
        unsigned em = eqw[tid], sel = 0;
        int rank = (int)(incl - wcnt[tid]);
        while (em) {
            int b = __ffs(em) - 1;
            if (rank < remaining) sel |= 1u << b;
            rank++;
            em &= em - 1;
        }
        bits[tid] = gtw[tid] | sel;
    }
}

// ---------------- kernel C: tensor-core masked flash attention ----------------
// 128-row q tiles. smem: Q 0..32K, vb@32768, sb@33280 (padded),
// stages @34816: each 32K = K(16K) V(16K). total 100352.
#define SM_Q  0
#define SM_VB 32768
#define SM_SB 33280
#define SM_ST 34816
#define SM_STSZ 32768
#define FL_BYTES (SM_ST + 2 * SM_STSZ)

__device__ __forceinline__ void load_stage(unsigned st, size_t hb, int jb, int tid) {
    #pragma unroll
    for (int i = 0; i < 8; i++) {
        int e = tid + i * 256;          // 0..2047
        int arr = e >> 10;              // 0:K 1:V
        int x = e & 1023;
        int r = x >> 4, c = x & 15;
        unsigned off = (unsigned)(r * 256 + ((c ^ (r & 7)) << 4));
        const unsigned* src = (arr ? g_v : g_k) + hb + (size_t)(jb + r) * 64 + c * 4;
        cpa16(st + (unsigned)arr * 16384u + off, src);
    }
}

__global__ void __launch_bounds__(256, 1)
flash_mma_kernel(float* __restrict__ out) {
    extern __shared__ unsigned char smem[];
    const unsigned sb0 = (unsigned)__cvta_generic_to_shared(smem);
    unsigned* vbm = (unsigned*)(smem + SM_VB);
    unsigned* sbm = (unsigned*)(smem + SM_SB);

    int bid = blockIdx.x;
    int h   = bid & 7;
    int itb = 31 - (bid >> 3);          // heavy-first
    int tid = threadIdx.x, lane = tid & 31, w = tid >> 5;
    int g = lane >> 2, t = lane & 3;
    const int qr0 = w * 16;
    const int i0g = itb * 128;
    const int iA = i0g + qr0 + g;
    const int it2 = 2 * itb + 1;
    const size_t hb = (size_t)h * SEQ * 64;

    if (tid < NW)            vbm[tid]      = g_vbits[h * NW + tid];
    else if (tid < 2 * NW)   sbm[tid - NW] = g_sbits[h * NW + tid - NW];
    if (tid < 8)             sbm[NW + tid] = 0u;   // pad for funnel reads

    // Q tile (128 rows) + stage 0, one commit group
    #pragma unroll
    for (int i = 0; i < 8; i++) {
        int e = tid + i * 256;
        int r = e >> 4, c = e & 15;
        unsigned off = (unsigned)(r * 256 + ((c ^ (r & 7)) << 4));
        cpa16(sb0 + SM_Q + off, &g_q[hb + (size_t)(i0g + r) * 64 + c * 4]);
    }
    load_stage(sb0 + SM_ST, hb, 0, tid);
    cpa_commit();
    cpa_wait0();
    __syncthreads();

    int am = (lane >> 3) & 1, ar = lane & 7, ac = lane >> 4;

    // hoisted Q fragments (invariant across jt)
    unsigned Qh[8][4];
    #pragma unroll
    for (int ks = 0; ks < 8; ks++) {
        int row = qr0 + am * 8 + ar, ch = ks * 2 + ac;
        ldsm4(Qh[ks], sb0 + SM_Q + row * 256 + ((ch ^ (row & 7)) << 4));
    }

    float O[16][4];
    #pragma unroll
    for (int o = 0; o < 16; o++) { O[o][0]=0;O[o][1]=0;O[o][2]=0;O[o][3]=0; }
    float lg = 0.f, lg8 = 0.f;
    const int ktrot = w & 3;

    for (int jt = 0; jt <= it2; jt++) {
        if (jt > 0) { cpa_wait0(); __syncthreads(); }
        unsigned st = sb0 + SM_ST + (jt & 1) * SM_STSZ;
        if (jt < it2) {
            load_stage(sb0 + SM_ST + ((jt + 1) & 1) * SM_STSZ, hb, (jt + 1) * 64, tid);
            cpa_commit();
        }

        int jb = jt * 64;
        // bit-parallel allow words, once per jt (rows iA and iA+8)
        unsigned vlo = vbm[jb >> 5], vhi = vbm[(jb >> 5) + 1];
        unsigned aloA, ahiA, aloB, ahiB;
        build_allow(iA - jb,     sbm, vlo, vhi, aloA, ahiA);
        build_allow(iA - jb + 8, sbm, vlo, vhi, aloB, ahiB);

        #pragma unroll
        for (int kk = 0; kk < 4; kk++) {
            int kt = (kk + ktrot) & 3;

            // ---- QK for this 16-key chunk ----
            float S0[4] = {0.f, 0.f, 0.f, 0.f};
            float S1[4] = {0.f, 0.f, 0.f, 0.f};
            #pragma unroll
            for (int ks = 0; ks < 8; ks++) {
                unsigned bh[4];
                int row = kt * 16 + am * 8 + ar, ch = ks * 2 + ac;
                ldsm4(bh, st + row * 256 + ((ch ^ (row & 7)) << 4));
                mma16(S0, Qh[ks], bh[0], bh[2]);
                mma16(S1, Qh[ks], bh[1], bh[3]);
            }

            // ---- mask (bit-parallel) + ex2 + single-pack epilogue ----
            unsigned aph[4];
            #pragma unroll
            for (int nn = 0; nn < 2; nn++) {
                float* S = nn ? S1 : S0;
                int n = kt * 2 + nn;
                int sh = (n & 3) * 8 + 2 * t;
                unsigned aA = ((n < 4) ? aloA : ahiA) >> sh;
                unsigned aB = ((n < 4) ? aloB : ahiB) >> sh;
                float p0, p1, p2, p3;
                asm("ex2.approx.ftz.f32 %0, %1;" : "=f"(p0) : "f"(S[0]));
                asm("ex2.approx.ftz.f32 %0, %1;" : "=f"(p1) : "f"(S[1]));
                asm("ex2.approx.ftz.f32 %0, %1;" : "=f"(p2) : "f"(S[2]));
                asm("ex2.approx.ftz.f32 %0, %1;" : "=f"(p3) : "f"(S[3]));
                p0 = (aA & 1u) ? p0 : 0.f;
                p1 = (aA & 2u) ? p1 : 0.f;
                p2 = (aB & 1u) ? p2 : 0.f;
                p3 = (aB & 2u) ? p3 : 0.f;
                __half2 hA = __floats2half2_rn(p0, p1);
                __half2 hB = __floats2half2_rn(p2, p3);
                float2 fA = __half22float2(hA);
                float2 fB = __half22float2(hB);
                lg  += fA.x + fA.y;
                lg8 += fB.x + fB.y;
                aph[nn * 2 + 0] = *(unsigned*)&hA;
                aph[nn * 2 + 1] = *(unsigned*)&hB;
            }

            // ---- PV for this chunk ----
            #pragma unroll
            for (int n2 = 0; n2 < 8; n2++) {
                unsigned vh4[4];
                int row = kt * 16 + am * 8 + ar, ch = n2 * 2 + ac;
                ldsm4t(vh4, st + 16384 + row * 256 + ((ch ^ (row & 7)) << 4));
                mma16(O[n2*2],   aph, vh4[0], vh4[1]);
                mma16(O[n2*2+1], aph, vh4[2], vh4[3]);
            }
        }
    }

    // ---- epilogue ----
    lg  += __shfl_xor_sync(0xffffffffu, lg, 1);  lg  += __shfl_xor_sync(0xffffffffu, lg, 2);
    lg8 += __shfl_xor_sync(0xffffffffu, lg8, 1); lg8 += __shfl_xor_sync(0xffffffffu, lg8, 2);
    float inv0 = 1.0f / lg, inv1 = 1.0f / lg8;
    size_t ob = (size_t)h * SEQ * DH;
    int r0 = i0g + qr0 + g, r1 = r0 + 8;
    #pragma unroll
    for (int o = 0; o < 16; o++) {
        *(float2*)&out[ob + (size_t)r0 * DH + o * 8 + 2 * t] =
            make_float2(O[o][0] * inv0, O[o][1] * inv0);
        *(float2*)&out[ob + (size_t)r1 * DH + o * 8 + 2 * t] =
            make_float2(O[o][2] * inv1, O[o][3] * inv1);
    }
}

// ---------------- launch ----------------
extern "C" void kernel_launch(void* const* d_in, const int* in_sizes, int n_in,
                              void* d_out, int out_size) {
    const float* q = (const float*)d_in[0];
    const float* k = (const float*)d_in[1];
    const float* v = (const float*)d_in[2];
    float* out = (float*)d_out;

    int psm = (64 * QS_STRIDE + 64 * 128) * 4;
    cudaFuncSetAttribute(pattern_kernel, cudaFuncAttributeMaxDynamicSharedMemorySize, psm);
    pattern_kernel<<<dim3(SEQ / 64, NH), 256, psm>>>(q, k, v);
    select_kernel<<<dim3(2, NH), 1024>>>();

    cudaFuncSetAttribute(flash_mma_kernel, cudaFuncAttributeMaxDynamicSharedMemorySize, FL_BYTES);
    flash_mma_kernel<<<32 * NH, 256, FL_BYTES>>>(out);
}